// round 12
// baseline (speedup 1.0000x reference)
#include <cuda_runtime.h>
#include <cuda_bf16.h>
#include <cstdint>

// Problem constants
#define B      64
#define T      512
#define DIM    512
#define VOCAB  32000

// ---------------- device scratch (no allocation allowed) ----------------
__device__ float g_xp [(size_t)T * B * DIM];   // [t][b][h]  67MB
__device__ float g_hid[(size_t)T * B * DIM];   // [t][b][h]  67MB

// ---------------- packed fp32x2 FMA (Blackwell FFMA2) ----------------
__device__ __forceinline__ void fma2(unsigned long long &d,
                                     unsigned long long a,
                                     unsigned long long b) {
    asm("fma.rn.f32x2 %0, %1, %2, %0;" : "+l"(d) : "l"(a), "l"(b));
}
__device__ __forceinline__ float sum2(unsigned long long v) {
    return __uint_as_float((unsigned)v) + __uint_as_float((unsigned)(v >> 32));
}
__device__ __forceinline__ unsigned long long pack2(float a) {
    unsigned long long r;
    asm("mov.b64 %0, {%1, %1};" : "=l"(r) : "f"(a));
    return r;
}
__device__ __forceinline__ float lo32(unsigned long long v) {
    return __uint_as_float((unsigned)v);
}
__device__ __forceinline__ float hi32(unsigned long long v) {
    return __uint_as_float((unsigned)(v >> 32));
}
__device__ __forceinline__ unsigned smem_u32(const void* p) {
    unsigned a;
    asm("{ .reg .u64 t; cvta.to.shared.u64 t, %1; cvt.u32.u64 %0, t; }"
        : "=r"(a) : "l"(p));
    return a;
}
__device__ __forceinline__ unsigned mapa_u32(unsigned a, unsigned rank) {
    unsigned d;
    asm("mapa.shared::cluster.u32 %0, %1, %2;" : "=r"(d) : "r"(a), "r"(rank));
    return d;
}
__device__ __forceinline__ void mbar_init(unsigned addr, unsigned count) {
    asm volatile("mbarrier.init.shared.b64 [%0], %1;" :: "r"(addr), "r"(count) : "memory");
}
__device__ __forceinline__ void mbar_expect(unsigned addr, unsigned bytes) {
    asm volatile("mbarrier.arrive.expect_tx.shared.b64 _, [%0], %1;"
                 :: "r"(addr), "r"(bytes) : "memory");
}
__device__ __forceinline__ void mbar_wait(unsigned addr, unsigned parity) {
    asm volatile(
        "{\n\t.reg .pred P;\n\t"
        "LW_%=:\n\t"
        "mbarrier.try_wait.parity.acquire.cta.shared::cta.b64 P, [%0], %1, 0x989680;\n\t"
        "@P bra LD_%=;\n\t"
        "bra LW_%=;\n\t"
        "LD_%=:\n\t}"
        :: "r"(addr), "r"(parity) : "memory");
}
__device__ __forceinline__ void bulk_copy_cluster(unsigned dst_cluster,
                                                  unsigned src_cta,
                                                  unsigned bytes,
                                                  unsigned rmbar_cluster) {
    asm volatile(
        "cp.async.bulk.shared::cluster.shared::cta.mbarrier::complete_tx::bytes "
        "[%0], [%1], %2, [%3];"
        :: "r"(dst_cluster), "r"(src_cta), "r"(bytes), "r"(rmbar_cluster)
        : "memory");
}

// =====================================================================
// Kernel 1: xp[t][b][h] = emb[x[b][t]] . W_ih[h] + b_ih[h] + b_hh[h]
// 128x128x16 tiles, 256 threads, 8x8 register blocking, f32x2 accumulate,
// double-buffered smem (1 sync per K-tile, LDG overlapped with compute).
// =====================================================================
#define GBM 128
#define GBN 128
#define GBK 16
#define GLD 132

__global__ __launch_bounds__(256) void gemm_xp_kernel(
    const int* __restrict__ x, const float* __restrict__ emb,
    const float* __restrict__ W_ih, const float* __restrict__ b_ih,
    const float* __restrict__ b_hh)
{
    __shared__ float As[2][GBK][GLD];
    __shared__ float Bs[2][GBK][GLD];
    __shared__ int   idxs[GBM];
    __shared__ float bias[GBN];

    const int tid = threadIdx.x;
    const int tx = tid & 15, ty = tid >> 4;
    const int m0 = blockIdx.y * GBM;
    const int n0 = blockIdx.x * GBN;

    if (tid < GBM) {
        int m = m0 + tid;
        int bb = m & 63, tt = m >> 6;
        idxs[tid] = x[bb * T + tt];
        bias[tid] = b_ih[n0 + tid] + b_hh[n0 + tid];
    }
    __syncthreads();

    unsigned long long acc[8][4];
#pragma unroll
    for (int i = 0; i < 8; ++i)
#pragma unroll
        for (int j = 0; j < 4; ++j) acc[i][j] = 0ull;

    const float4* emb4 = reinterpret_cast<const float4*>(emb);
    const float4* wih4 = reinterpret_cast<const float4*>(W_ih);

    int mmv[2], kqv[2];
#pragma unroll
    for (int r = 0; r < 2; ++r) {
        int f = r * 256 + tid;
        mmv[r] = f >> 2; kqv[r] = f & 3;
    }

    float4 av[2], bv[2];
#pragma unroll
    for (int r = 0; r < 2; ++r) {
        av[r] = __ldg(&emb4[(size_t)idxs[mmv[r]] * (DIM / 4) + kqv[r]]);
        bv[r] = __ldg(&wih4[(size_t)(n0 + mmv[r]) * (DIM / 4) + kqv[r]]);
    }
#pragma unroll
    for (int r = 0; r < 2; ++r) {
        int mm = mmv[r], kc = kqv[r] * 4;
        As[0][kc + 0][mm] = av[r].x; As[0][kc + 1][mm] = av[r].y;
        As[0][kc + 2][mm] = av[r].z; As[0][kc + 3][mm] = av[r].w;
        Bs[0][kc + 0][mm] = bv[r].x; Bs[0][kc + 1][mm] = bv[r].y;
        Bs[0][kc + 2][mm] = bv[r].z; Bs[0][kc + 3][mm] = bv[r].w;
    }
    __syncthreads();

    const int NT = DIM / GBK;
    for (int kt = 0; kt < NT; ++kt) {
        const int cur = kt & 1;
        if (kt < NT - 1) {
            int kq = (kt + 1) * 4;
#pragma unroll
            for (int r = 0; r < 2; ++r) {
                av[r] = __ldg(&emb4[(size_t)idxs[mmv[r]] * (DIM / 4) + kq + kqv[r]]);
                bv[r] = __ldg(&wih4[(size_t)(n0 + mmv[r]) * (DIM / 4) + kq + kqv[r]]);
            }
        }

#pragma unroll
        for (int kk = 0; kk < GBK; ++kk) {
            float4 a0 = *reinterpret_cast<const float4*>(&As[cur][kk][ty * 4]);
            float4 a1 = *reinterpret_cast<const float4*>(&As[cur][kk][64 + ty * 4]);
            float4 b0 = *reinterpret_cast<const float4*>(&Bs[cur][kk][tx * 4]);
            float4 b1 = *reinterpret_cast<const float4*>(&Bs[cur][kk][64 + tx * 4]);
            ulonglong2 bp0 = *reinterpret_cast<ulonglong2*>(&b0);
            ulonglong2 bp1 = *reinterpret_cast<ulonglong2*>(&b1);
            float avv[8] = {a0.x, a0.y, a0.z, a0.w, a1.x, a1.y, a1.z, a1.w};
#pragma unroll
            for (int i = 0; i < 8; ++i) {
                unsigned long long ap = pack2(avv[i]);
                fma2(acc[i][0], ap, bp0.x);
                fma2(acc[i][1], ap, bp0.y);
                fma2(acc[i][2], ap, bp1.x);
                fma2(acc[i][3], ap, bp1.y);
            }
        }

        if (kt < NT - 1) {
            const int nxt = 1 - cur;
#pragma unroll
            for (int r = 0; r < 2; ++r) {
                int mm = mmv[r], kc = kqv[r] * 4;
                As[nxt][kc + 0][mm] = av[r].x; As[nxt][kc + 1][mm] = av[r].y;
                As[nxt][kc + 2][mm] = av[r].z; As[nxt][kc + 3][mm] = av[r].w;
                Bs[nxt][kc + 0][mm] = bv[r].x; Bs[nxt][kc + 1][mm] = bv[r].y;
                Bs[nxt][kc + 2][mm] = bv[r].z; Bs[nxt][kc + 3][mm] = bv[r].w;
            }
            __syncthreads();
        }
    }

    float4 bs0 = *reinterpret_cast<const float4*>(&bias[tx * 4]);
    float4 bs1 = *reinterpret_cast<const float4*>(&bias[64 + tx * 4]);
#pragma unroll
    for (int i = 0; i < 8; ++i) {
        int m = m0 + ((i < 4) ? (ty * 4 + i) : (64 + ty * 4 + (i - 4)));
        float4 o0, o1;
        o0.x = lo32(acc[i][0]) + bs0.x;  o0.y = hi32(acc[i][0]) + bs0.y;
        o0.z = lo32(acc[i][1]) + bs0.z;  o0.w = hi32(acc[i][1]) + bs0.w;
        o1.x = lo32(acc[i][2]) + bs1.x;  o1.y = hi32(acc[i][2]) + bs1.y;
        o1.z = lo32(acc[i][3]) + bs1.z;  o1.w = hi32(acc[i][3]) + bs1.w;
        *reinterpret_cast<float4*>(&g_xp[(size_t)m * DIM + n0 + tx * 4])      = o0;
        *reinterpret_cast<float4*>(&g_xp[(size_t)m * DIM + n0 + 64 + tx * 4]) = o1;
    }
}

// =====================================================================
// Kernel 2: persistent RNN over 8-CTA clusters; h exchange = DSMEM BULK
// copy (cp.async.bulk smem->smem, one 1KB tx per peer) + parity mbarrier.
// Grid: x=8 slices (cluster), y=16 groups. 512 threads/CTA.
// hsm layout [buf][src_slice*256 + b*64 + col] -> each peer's slice is a
// CONTIGUOUS 1KB block (bulk-copy friendly). Thread (h=tid&63, js=tid>>6)
// owns W_hh[hs0+h][js*64..+64) in 32 f32x2 regs; matvec reads slice js.
// =====================================================================
#define RNN_GROUPS 16
#define RNN_SLICES 8

__global__ __launch_bounds__(512, 1) __cluster_dims__(RNN_SLICES, 1, 1)
void rnn_kernel(const float* __restrict__ W_hh)
{
    __shared__ __align__(16) float hsm[2][8 * 256];     // 16KB recv buffers
    __shared__ float part[2][8 * 4 * 64];               // 16KB [parity][js][b][h]
    __shared__ __align__(16) float stage[2][256];       // 2KB outgoing slice [b][h]
    __shared__ __align__(8) unsigned long long mbar[2]; // per-buffer parity mbar

    const int tid   = threadIdx.x;
    const int slice = blockIdx.x;       // cluster rank
    const int g     = blockIdx.y;
    const int hs0   = slice * 64;
    const int b0    = g * 4;
    const int h     = tid & 63;
    const int js    = tid >> 6;         // 0..7, warp-uniform
    const int ob    = js & 3;           // output batch for tid<256

    // --- W segment in registers: 64 floats = 32 f32x2 ---
    unsigned long long w[32];
    {
        const float4* Wg4 = reinterpret_cast<const float4*>(W_hh)
                            + (size_t)(hs0 + h) * (DIM / 4) + js * 16;
#pragma unroll
        for (int k = 0; k < 16; ++k) {
            float4 v = __ldg(&Wg4[k]);
            ulonglong2 p = *reinterpret_cast<ulonglong2*>(&v);
            w[2 * k]     = p.x;
            w[2 * k + 1] = p.y;
        }
    }

    // h(0) = 0
#pragma unroll
    for (int r = 0; r < 4; ++r) hsm[0][r * 512 + tid] = 0.0f;

    const unsigned hsm_base   = smem_u32(hsm);
    const unsigned stage_base = smem_u32(stage);
    const unsigned mbar_base  = smem_u32(mbar);

    if (tid == 0) {
        mbar_init(mbar_base + 0, 1);
        mbar_init(mbar_base + 8, 1);
        // initial expects: buf1 consumed at t=1, buf0 at t=2 (both phase 0)
        mbar_expect(mbar_base + 8, 8192);
        mbar_expect(mbar_base + 0, 8192);
    }
    __syncthreads();
    asm volatile("barrier.cluster.arrive.aligned;" ::: "memory");
    asm volatile("barrier.cluster.wait.aligned;"   ::: "memory");

    // issuing threads (tid<8): remote dst = peer hsm slot for OUR slice
    unsigned rem_dst0 = 0, rem_dst1 = 0, rem_mb0 = 0, rem_mb1 = 0;
    if (tid < 8) {
        unsigned rh = mapa_u32(hsm_base,  (unsigned)tid);
        unsigned rm = mapa_u32(mbar_base, (unsigned)tid);
        rem_dst0 = rh + (unsigned)(slice * 256) * 4u;            // buf0 slot
        rem_dst1 = rh + (unsigned)(2048 + slice * 256) * 4u;     // buf1 slot
        rem_mb0  = rm;
        rem_mb1  = rm + 8;
    }

    int ph0 = 0, ph1 = 0;

    for (int t = 0; t < T; ++t) {
        const int cur = t & 1;

        // ---- prefetch xp (DRAM latency hidden behind wait+matvec) ----
        float xpv = 0.0f;
        if (tid < 256)
            xpv = __ldg(&g_xp[((size_t)t * B + (b0 + ob)) * DIM + hs0 + h]);

        // ---- wait all 8 slices for this step (data already in hsm) ----
        if (t > 0) {
            unsigned ma = mbar_base + (unsigned)(cur * 8);
            int p = cur ? ph1 : ph0;
            mbar_wait(ma, (unsigned)p);
            if (cur) ph1 ^= 1; else ph0 ^= 1;
            if (tid == 0 && t + 2 < T)      // repost for this buffer's next use
                mbar_expect(ma, 8192);
        }

        // ---- matvec: W regs x H broadcast-LDS (slice js, 4 batches) ----
        const ulonglong2* Hs = reinterpret_cast<const ulonglong2*>(
            &hsm[cur][js * 256]);   // [b*16 + k] in 16B units
        unsigned long long a0x=0,a0y=0,a1x=0,a1y=0,a2x=0,a2y=0,a3x=0,a3y=0;
#pragma unroll
        for (int k = 0; k < 16; ++k) {
            ulonglong2 x0 = Hs[k];
            fma2(a0x, w[2*k], x0.x); fma2(a0y, w[2*k+1], x0.y);
            ulonglong2 x1 = Hs[16 + k];
            fma2(a1x, w[2*k], x1.x); fma2(a1y, w[2*k+1], x1.y);
            ulonglong2 x2 = Hs[32 + k];
            fma2(a2x, w[2*k], x2.x); fma2(a2y, w[2*k+1], x2.y);
            ulonglong2 x3 = Hs[48 + k];
            fma2(a3x, w[2*k], x3.x); fma2(a3y, w[2*k+1], x3.y);
        }
        part[cur][(js * 4 + 0) * 64 + h] = sum2(a0x) + sum2(a0y);
        part[cur][(js * 4 + 1) * 64 + h] = sum2(a1x) + sum2(a1y);
        part[cur][(js * 4 + 2) * 64 + h] = sum2(a2x) + sum2(a2y);
        part[cur][(js * 4 + 3) * 64 + h] = sum2(a3x) + sum2(a3y);
        __syncthreads();   // join; warps 8-15 may run ahead (part parity-safe)

        // ---- reduce, tanh, stage, bulk-push to all 8 cluster CTAs ----
        if (tid < 256) {
            float dot = 0.0f;
#pragma unroll
            for (int s = 0; s < 8; ++s) dot += part[cur][(s * 4 + ob) * 64 + h];
            float hn = tanhf(dot + xpv);
            stage[cur][ob * 64 + h] = hn;
            asm volatile("bar.sync 9, 256;" ::: "memory");   // writers join
            if (tid < 8 && t < T - 1) {
                asm volatile("fence.proxy.async.shared::cta;" ::: "memory");
                const int nxt = 1 - cur;
                unsigned src = stage_base + (unsigned)(cur * 256) * 4u;
                bulk_copy_cluster(nxt ? rem_dst1 : rem_dst0, src, 1024,
                                  nxt ? rem_mb1 : rem_mb0);
            }
            // lazy history store (off the critical exchange path)
            g_hid[((size_t)t * B + (b0 + ob)) * DIM + hs0 + h] = hn;
        }
    }
}

// =====================================================================
// Kernel 3: softmax over H (axis=1 of [B,H,T]) + transpose -> [b][h][t]
// =====================================================================
__global__ __launch_bounds__(256) void softmax_kernel(float* __restrict__ out)
{
    __shared__ float tile[16][513];
    __shared__ float rinv[16];

    const int tid = threadIdx.x;
    const int bb  = blockIdx.y;
    const int t0  = blockIdx.x * 16;

#pragma unroll
    for (int it = 0; it < 32; ++it) {
        int f = it * 256 + tid;
        int tt = f >> 9, hh = f & 511;
        tile[tt][hh] = __ldg(&g_hid[((size_t)(t0 + tt) * B + bb) * DIM + hh]);
    }
    __syncthreads();

    const int wid = tid >> 5, lane = tid & 31;
#pragma unroll
    for (int rr = 0; rr < 2; ++rr) {
        int tt = wid * 2 + rr;
        float m = -3.4e38f;
#pragma unroll
        for (int k = 0; k < 16; ++k) m = fmaxf(m, tile[tt][lane + 32 * k]);
#pragma unroll
        for (int off = 16; off >= 1; off >>= 1)
            m = fmaxf(m, __shfl_xor_sync(0xffffffffu, m, off));
        float s = 0.0f;
#pragma unroll
        for (int k = 0; k < 16; ++k) {
            float e = __expf(tile[tt][lane + 32 * k] - m);
            tile[tt][lane + 32 * k] = e;
            s += e;
        }
#pragma unroll
        for (int off = 16; off >= 1; off >>= 1)
            s += __shfl_xor_sync(0xffffffffu, s, off);
        if (lane == 0) rinv[tt] = 1.0f / s;
    }
    __syncthreads();

    const int hw  = tid >> 4;
    const int l16 = tid & 15;
#pragma unroll
    for (int it = 0; it < 32; ++it) {
        int hh = it * 16 + hw;
        float v = tile[l16][hh] * rinv[l16];
        out[((size_t)bb * DIM + hh) * T + t0 + l16] = v;
    }
}

// =====================================================================
extern "C" void kernel_launch(void* const* d_in, const int* in_sizes, int n_in,
                              void* d_out, int out_size)
{
    const int*   x    = (const int*)  d_in[0];
    const float* emb  = (const float*)d_in[1];
    const float* W_ih = (const float*)d_in[2];
    const float* W_hh = (const float*)d_in[3];
    const float* b_ih = (const float*)d_in[4];
    const float* b_hh = (const float*)d_in[5];
    float* out = (float*)d_out;

    // 1) input projection GEMM -> g_xp
    gemm_xp_kernel<<<dim3(DIM / GBN, (T * B) / GBM), 256>>>(x, emb, W_ih, b_ih, b_hh);

    // 2) persistent recurrence (16 clusters of 8 CTAs, DSMEM bulk exchange)
    rnn_kernel<<<dim3(RNN_SLICES, RNN_GROUPS), 512>>>(W_hh);

    // 3) softmax over H + transpose -> out
    softmax_kernel<<<dim3(T / 16, B), 256>>>(out);
}

// round 15
// speedup vs baseline: 1.0013x; 1.0013x over previous
#include <cuda_runtime.h>
#include <cuda_bf16.h>
#include <cstdint>

// Problem constants
#define B      64
#define T      512
#define DIM    512
#define VOCAB  32000

// ---------------- device scratch (no allocation allowed) ----------------
__device__ float    g_hid [(size_t)T * B * DIM];   // [t][b][h]  67MB
__device__ float    g_hbuf[2 * B * DIM];           // double-buffered h state
__device__ unsigned g_flag[(size_t)T * 8 * 16 * 8];  // (t,slice,g), 32B stride

// ---------------- packed fp32x2 FMA (Blackwell FFMA2) ----------------
__device__ __forceinline__ void fma2(unsigned long long &d,
                                     unsigned long long a,
                                     unsigned long long b) {
    asm("fma.rn.f32x2 %0, %1, %2, %0;" : "+l"(d) : "l"(a), "l"(b));
}
__device__ __forceinline__ float sum2(unsigned long long v) {
    return __uint_as_float((unsigned)v) + __uint_as_float((unsigned)(v >> 32));
}

#define RNN_GROUPS 16
#define RNN_SLICES 8

// dynamic smem layout (float offsets)
#define WIH_STRIDE 516                    // 129 x 16B (odd) -> conflict-free cols
#define SM_WIH   0                        // 64 rows x 516        = 33024
#define SM_HSM   33024                    // 4 x 512              =  2048
#define SM_PART  35072                    // 2 x 2048             =  4096
#define SM_PXP   39168                    // 8*4*64               =  2048
#define SM_EMB   41216                    // 2 x 4 x 512          =  4096
#define SM_XIDX  45312                    // 4 x 512 ints         =  2048
#define SM_TOTALF 47360
#define SM_BYTES (SM_TOTALF * 4)          // 189440 B

__device__ __forceinline__ unsigned flag_idx(int t, int s, int g) {
    return (unsigned)(((t * 8 + s) * 16 + g) * 8);
}

// =====================================================================
// Fused persistent kernel: RNN recurrence with the input-projection
// GEMM folded into each step's exchange-latency shadow (phase 5).
// Grid: (8 slices, 16 groups) = 128 co-resident CTAs, 512 threads.
// Thread (h=tid&63, js=tid>>6) owns W_hh[hs0+h][js*64..+64) in 32 f32x2
// registers; W_ih[hs0..+64)[*] lives in smem (padded stride).
// Per step t:
//   1. gate: per-js lane-0 acquire-poll flag(t), ldcg 1KB h slice  (R11)
//   2. matvec -> part[t&1]            (~1024 fma cyc)
//   3. __syncthreads (join)
//   4. reducers (tid<256): reduce, hn=tanh(dot+xp_reg), STG g_hbuf,
//      bar9, tid0 st.release flag(t+1), STG g_hid      (R11 protocol)
//   5. ALL: compute xp[t+1] partials from smem W_ih x staged emb rows,
//      stage emb rows for t+2, __syncthreads, reducers fold partials
//      + bias into xp_reg.    <- overlaps the L2 flag/h round-trips
// =====================================================================
__global__ __launch_bounds__(512, 1) void rnn_kernel(
    const float* __restrict__ W_hh, const float* __restrict__ W_ih,
    const float* __restrict__ emb,  const int* __restrict__ x,
    const float* __restrict__ b_ih, const float* __restrict__ b_hh)
{
    extern __shared__ __align__(16) float sm[];
    float* Wih    = sm + SM_WIH;
    float* hsm    = sm + SM_HSM;
    float* part   = sm + SM_PART;     // [parity][js][b][h]
    float* partxp = sm + SM_PXP;      // [js][b][h]
    float* embsm  = sm + SM_EMB;      // [slot][b][512]
    int*   xidx   = (int*)(sm + SM_XIDX);   // [b][T]

    const int tid   = threadIdx.x;
    const int slice = blockIdx.x;
    const int g     = blockIdx.y;
    const int hs0   = slice * 64;
    const int b0    = g * 4;
    const int h     = tid & 63;
    const int js    = tid >> 6;      // 0..7, warp-uniform
    const int ob    = js & 3;        // output batch for tid<256
    const int sb    = tid >> 7;      // staging batch 0..3
    const int sc    = tid & 127;     // staging float4 chunk

    const float4* wih4 = reinterpret_cast<const float4*>(W_ih);
    const float4* emb4 = reinterpret_cast<const float4*>(emb);
    const int4*   x4   = reinterpret_cast<const int4*>(x);

    // --- W_hh segment in registers: 64 floats = 32 f32x2 ---
    unsigned long long w[32];
    {
        const float4* Wg4 = reinterpret_cast<const float4*>(W_hh)
                            + (size_t)(hs0 + h) * (DIM / 4) + js * 16;
#pragma unroll
        for (int k = 0; k < 16; ++k) {
            float4 v = __ldg(&Wg4[k]);
            ulonglong2 p = *reinterpret_cast<ulonglong2*>(&v);
            w[2 * k]     = p.x;
            w[2 * k + 1] = p.y;
        }
    }

    // --- W_ih slice -> smem (padded rows): 64 rows x 128 float4 = 8192 ---
#pragma unroll
    for (int i = 0; i < 16; ++i) {
        int idx = i * 512 + tid;            // 0..8191
        int r = idx >> 7, c = idx & 127;    // r 0..63, c 0..127
        float4 v = __ldg(&wih4[(size_t)(hs0 + r) * 128 + c]);
        *reinterpret_cast<float4*>(&Wih[r * WIH_STRIDE + c * 4]) = v;
    }
    // --- x indices for our 4 batches, all T ---
    {
        int4 v = __ldg(&x4[(size_t)(b0 + sb) * (T / 4) + sc]);
        *reinterpret_cast<int4*>(&xidx[sb * T + sc * 4]) = v;
    }
    // --- bias reg for reducers ---
    float bias_reg = 0.0f;
    if (tid < 256)
        bias_reg = __ldg(&b_ih[hs0 + h]) + __ldg(&b_hh[hs0 + h]);

    // h(0) = 0
#pragma unroll
    for (int r = 0; r < 4; ++r) hsm[r * 512 + tid] = 0.0f;
    __syncthreads();

    // --- stage emb rows for t=0 into embsm slot 0 ---
    {
        int xi = xidx[sb * T + 0];
        float4 v = __ldg(&emb4[(size_t)xi * 128 + sc]);
        *reinterpret_cast<float4*>(&embsm[0 * 2048 + sb * 512 + sc * 4]) = v;
    }
    __syncthreads();

    float xp_reg = 0.0f;

    // ============ phase-5 body as a macro (tn = timestep computed) ======
#define PHASE5(tn_) do {                                                    \
        const int tn = (tn_);                                               \
        float4 ev;                                                          \
        const int stg = (tn + 1 < T);                                       \
        if (stg) {                                                          \
            int xi = xidx[sb * T + tn + 1];                                 \
            ev = __ldg(&emb4[(size_t)xi * 128 + sc]);                       \
        }                                                                   \
        const float* EW = &Wih[h * WIH_STRIDE + js * 64];                   \
        const float* EB = &embsm[(tn & 1) * 2048 + js * 64];                \
        unsigned long long c0x=0,c0y=0,c1x=0,c1y=0,c2x=0,c2y=0,c3x=0,c3y=0; \
        _Pragma("unroll")                                                   \
        for (int k = 0; k < 16; ++k) {                                      \
            float4 wv = *reinterpret_cast<const float4*>(&EW[k * 4]);       \
            ulonglong2 wp = *reinterpret_cast<ulonglong2*>(&wv);            \
            float4 e0 = *reinterpret_cast<const float4*>(&EB[k * 4]);       \
            ulonglong2 p0 = *reinterpret_cast<ulonglong2*>(&e0);            \
            fma2(c0x, wp.x, p0.x); fma2(c0y, wp.y, p0.y);                   \
            float4 e1 = *reinterpret_cast<const float4*>(&EB[512 + k * 4]); \
            ulonglong2 p1 = *reinterpret_cast<ulonglong2*>(&e1);            \
            fma2(c1x, wp.x, p1.x); fma2(c1y, wp.y, p1.y);                   \
            float4 e2 = *reinterpret_cast<const float4*>(&EB[1024 + k * 4]);\
            ulonglong2 p2 = *reinterpret_cast<ulonglong2*>(&e2);            \
            fma2(c2x, wp.x, p2.x); fma2(c2y, wp.y, p2.y);                   \
            float4 e3 = *reinterpret_cast<const float4*>(&EB[1536 + k * 4]);\
            ulonglong2 p3 = *reinterpret_cast<ulonglong2*>(&e3);            \
            fma2(c3x, wp.x, p3.x); fma2(c3y, wp.y, p3.y);                   \
        }                                                                   \
        partxp[(js * 4 + 0) * 64 + h] = sum2(c0x) + sum2(c0y);              \
        partxp[(js * 4 + 1) * 64 + h] = sum2(c1x) + sum2(c1y);              \
        partxp[(js * 4 + 2) * 64 + h] = sum2(c2x) + sum2(c2y);              \
        partxp[(js * 4 + 3) * 64 + h] = sum2(c3x) + sum2(c3y);              \
        if (stg)                                                            \
            *reinterpret_cast<float4*>(                                     \
                &embsm[((tn + 1) & 1) * 2048 + sb * 512 + sc * 4]) = ev;    \
        __syncthreads();                                                    \
        if (tid < 256) {                                                    \
            float s = 0.0f;                                                 \
            _Pragma("unroll")                                               \
            for (int q = 0; q < 8; ++q) s += partxp[(q * 4 + ob) * 64 + h]; \
            xp_reg = s + bias_reg;                                          \
        }                                                                   \
    } while (0)

    // prologue: xp[0] -> xp_reg (also stages emb for t=1)
    PHASE5(0);

    // per-js slice-load coords for the gate: 64 threads x float4 = 1KB
    const int lb  = h >> 4;
    const int lc  = (h & 15) * 4;
    const int cbK = js * 16;

    for (int t = 0; t < T; ++t) {
        const int cur = t & 1;

        // ---- 1. gate (R11): lane-0 acquire-poll, then group load ----
        if (t > 0) {
            if (h == 0) {
                const unsigned* fp = &g_flag[flag_idx(t, js, g)];
                unsigned v;
                do {
                    asm volatile("ld.acquire.gpu.global.u32 %0, [%1];"
                                 : "=r"(v) : "l"(fp) : "memory");
                } while (!v);
            }
            asm volatile("bar.sync %0, %1;" :: "r"(js + 1), "r"(64) : "memory");
            const float4* src = reinterpret_cast<const float4*>(
                &g_hbuf[(size_t)cur * B * DIM
                        + (size_t)(b0 + lb) * DIM + js * 64 + lc]);
            float4 hv = __ldcg(src);
            *reinterpret_cast<float4*>(&hsm[lb * 512 + js * 64 + lc]) = hv;
            asm volatile("bar.sync %0, %1;" :: "r"(js + 1), "r"(64) : "memory");
        }

        // ---- 2. matvec: W_hh regs x H broadcast-LDS ----
        const ulonglong2* H2 = reinterpret_cast<const ulonglong2*>(hsm);
        unsigned long long a0x=0,a0y=0,a1x=0,a1y=0,a2x=0,a2y=0,a3x=0,a3y=0;
#pragma unroll
        for (int k = 0; k < 16; ++k) {
            int c = cbK + k;
            ulonglong2 x0 = H2[c];
            fma2(a0x, w[2*k], x0.x); fma2(a0y, w[2*k+1], x0.y);
            ulonglong2 x1 = H2[128 + c];
            fma2(a1x, w[2*k], x1.x); fma2(a1y, w[2*k+1], x1.y);
            ulonglong2 x2 = H2[256 + c];
            fma2(a2x, w[2*k], x2.x); fma2(a2y, w[2*k+1], x2.y);
            ulonglong2 x3 = H2[384 + c];
            fma2(a3x, w[2*k], x3.x); fma2(a3y, w[2*k+1], x3.y);
        }
        float* pc = &part[cur * 2048];
        pc[(js * 4 + 0) * 64 + h] = sum2(a0x) + sum2(a0y);
        pc[(js * 4 + 1) * 64 + h] = sum2(a1x) + sum2(a1y);
        pc[(js * 4 + 2) * 64 + h] = sum2(a2x) + sum2(a2y);
        pc[(js * 4 + 3) * 64 + h] = sum2(a3x) + sum2(a3y);
        __syncthreads();   // 3. join (part parity lets warps run ahead)

        // ---- 4. reduce, tanh(+xp_reg), publish, release (R11) ----
        if (tid < 256) {
            float dot = 0.0f;
#pragma unroll
            for (int s = 0; s < 8; ++s) dot += pc[(s * 4 + ob) * 64 + h];
            float hn = tanhf(dot + xp_reg);
            if (t < T - 1)
                g_hbuf[(size_t)((t + 1) & 1) * B * DIM
                       + (size_t)(b0 + ob) * DIM + hs0 + h] = hn;
            asm volatile("bar.sync 9, 256;" ::: "memory");
            if (tid == 0 && t < T - 1) {
                unsigned* fp = &g_flag[flag_idx(t + 1, slice, g)];
                asm volatile("st.release.gpu.global.u32 [%0], %1;"
                             :: "l"(fp), "r"(1u) : "memory");
            }
            g_hid[((size_t)t * B + (b0 + ob)) * DIM + hs0 + h] = hn;
        }

        // ---- 5. fused xp[t+1] compute in the exchange shadow ----
        if (t < T - 1) PHASE5(t + 1);
    }
#undef PHASE5
}

// =====================================================================
// softmax over H (axis=1 of [B,H,T]) + transpose [t][b][h] -> [b][h][t]
// =====================================================================
__global__ __launch_bounds__(256) void softmax_kernel(float* __restrict__ out)
{
    __shared__ float tile[16][513];
    __shared__ float rinv[16];

    const int tid = threadIdx.x;
    const int bb  = blockIdx.y;
    const int t0  = blockIdx.x * 16;

#pragma unroll
    for (int it = 0; it < 32; ++it) {
        int f = it * 256 + tid;
        int tt = f >> 9, hh = f & 511;
        tile[tt][hh] = __ldg(&g_hid[((size_t)(t0 + tt) * B + bb) * DIM + hh]);
    }
    __syncthreads();

    const int wid = tid >> 5, lane = tid & 31;
#pragma unroll
    for (int rr = 0; rr < 2; ++rr) {
        int tt = wid * 2 + rr;
        float m = -3.4e38f;
#pragma unroll
        for (int k = 0; k < 16; ++k) m = fmaxf(m, tile[tt][lane + 32 * k]);
#pragma unroll
        for (int off = 16; off >= 1; off >>= 1)
            m = fmaxf(m, __shfl_xor_sync(0xffffffffu, m, off));
        float s = 0.0f;
#pragma unroll
        for (int k = 0; k < 16; ++k) {
            float e = __expf(tile[tt][lane + 32 * k] - m);
            tile[tt][lane + 32 * k] = e;
            s += e;
        }
#pragma unroll
        for (int off = 16; off >= 1; off >>= 1)
            s += __shfl_xor_sync(0xffffffffu, s, off);
        if (lane == 0) rinv[tt] = 1.0f / s;
    }
    __syncthreads();

    const int hw  = tid >> 4;
    const int l16 = tid & 15;
#pragma unroll
    for (int it = 0; it < 32; ++it) {
        int hh = it * 16 + hw;
        float v = tile[l16][hh] * rinv[l16];
        out[((size_t)bb * DIM + hh) * T + t0 + l16] = v;
    }
}

// =====================================================================
extern "C" void kernel_launch(void* const* d_in, const int* in_sizes, int n_in,
                              void* d_out, int out_size)
{
    const int*   x    = (const int*)  d_in[0];
    const float* emb  = (const float*)d_in[1];
    const float* W_ih = (const float*)d_in[2];
    const float* W_hh = (const float*)d_in[3];
    const float* b_ih = (const float*)d_in[4];
    const float* b_hh = (const float*)d_in[5];
    float* out = (float*)d_out;

    void* p_flag;
    cudaGetSymbolAddress(&p_flag, g_flag);
    cudaMemsetAsync(p_flag, 0, sizeof(unsigned) * (size_t)T * 8 * 16 * 8);

    cudaFuncSetAttribute(rnn_kernel,
                         cudaFuncAttributeMaxDynamicSharedMemorySize,
                         SM_BYTES);

    // 1) fused persistent recurrence + input projection -> g_hid
    rnn_kernel<<<dim3(RNN_SLICES, RNN_GROUPS), 512, SM_BYTES>>>(
        W_hh, W_ih, emb, x, b_ih, b_hh);

    // 2) softmax over H + transpose -> out
    softmax_kernel<<<dim3(T / 16, B), 256>>>(out);
}

// round 17
// speedup vs baseline: 1.2930x; 1.2914x over previous
#include <cuda_runtime.h>
#include <cuda_bf16.h>
#include <cstdint>

// Problem constants
#define B      64
#define T      512
#define DIM    512
#define VOCAB  32000

// ---------------- device scratch (no allocation allowed) ----------------
__device__ float    g_xp  [(size_t)T * B * DIM];   // [t][b][h]  67MB
__device__ float    g_hid [(size_t)T * B * DIM];   // [t][b][h]  67MB
__device__ float    g_hbuf[2 * B * DIM];           // double-buffered h state
__device__ unsigned g_flag[(size_t)T * 8 * 16 * 8];  // (t,slice,g), 32B stride

// ---------------- packed fp32x2 FMA (Blackwell FFMA2) ----------------
__device__ __forceinline__ void fma2(unsigned long long &d,
                                     unsigned long long a,
                                     unsigned long long b) {
    asm("fma.rn.f32x2 %0, %1, %2, %0;" : "+l"(d) : "l"(a), "l"(b));
}
__device__ __forceinline__ float sum2(unsigned long long v) {
    return __uint_as_float((unsigned)v) + __uint_as_float((unsigned)(v >> 32));
}
__device__ __forceinline__ unsigned long long pack2(float a) {
    unsigned long long r;
    asm("mov.b64 %0, {%1, %1};" : "=l"(r) : "f"(a));
    return r;
}
__device__ __forceinline__ float lo32(unsigned long long v) {
    return __uint_as_float((unsigned)v);
}
__device__ __forceinline__ float hi32(unsigned long long v) {
    return __uint_as_float((unsigned)(v >> 32));
}

// =====================================================================
// Kernel 1: xp[t][b][h] = emb[x[b][t]] . W_ih[h] + b_ih[h] + b_hh[h]
// 128x128x16 tiles, 256 threads, 8x8 register blocking, f32x2 accumulate,
// double-buffered smem (1 sync per K-tile, LDG overlapped with compute).
// (proven config: 292 us, fma pipe 73.7%)
// =====================================================================
#define GBM 128
#define GBN 128
#define GBK 16
#define GLD 132

__global__ __launch_bounds__(256) void gemm_xp_kernel(
    const int* __restrict__ x, const float* __restrict__ emb,
    const float* __restrict__ W_ih, const float* __restrict__ b_ih,
    const float* __restrict__ b_hh)
{
    __shared__ float As[2][GBK][GLD];
    __shared__ float Bs[2][GBK][GLD];
    __shared__ int   idxs[GBM];
    __shared__ float bias[GBN];

    const int tid = threadIdx.x;
    const int tx = tid & 15, ty = tid >> 4;
    const int m0 = blockIdx.y * GBM;
    const int n0 = blockIdx.x * GBN;

    if (tid < GBM) {
        int m = m0 + tid;
        int bb = m & 63, tt = m >> 6;
        idxs[tid] = x[bb * T + tt];
        bias[tid] = b_ih[n0 + tid] + b_hh[n0 + tid];
    }
    __syncthreads();

    unsigned long long acc[8][4];
#pragma unroll
    for (int i = 0; i < 8; ++i)
#pragma unroll
        for (int j = 0; j < 4; ++j) acc[i][j] = 0ull;

    const float4* emb4 = reinterpret_cast<const float4*>(emb);
    const float4* wih4 = reinterpret_cast<const float4*>(W_ih);

    int mmv[2], kqv[2];
#pragma unroll
    for (int r = 0; r < 2; ++r) {
        int f = r * 256 + tid;
        mmv[r] = f >> 2; kqv[r] = f & 3;
    }

    float4 av[2], bv[2];
#pragma unroll
    for (int r = 0; r < 2; ++r) {
        av[r] = __ldg(&emb4[(size_t)idxs[mmv[r]] * (DIM / 4) + kqv[r]]);
        bv[r] = __ldg(&wih4[(size_t)(n0 + mmv[r]) * (DIM / 4) + kqv[r]]);
    }
#pragma unroll
    for (int r = 0; r < 2; ++r) {
        int mm = mmv[r], kc = kqv[r] * 4;
        As[0][kc + 0][mm] = av[r].x; As[0][kc + 1][mm] = av[r].y;
        As[0][kc + 2][mm] = av[r].z; As[0][kc + 3][mm] = av[r].w;
        Bs[0][kc + 0][mm] = bv[r].x; Bs[0][kc + 1][mm] = bv[r].y;
        Bs[0][kc + 2][mm] = bv[r].z; Bs[0][kc + 3][mm] = bv[r].w;
    }
    __syncthreads();

    const int NT = DIM / GBK;
    for (int kt = 0; kt < NT; ++kt) {
        const int cur = kt & 1;
        if (kt < NT - 1) {
            int kq = (kt + 1) * 4;
#pragma unroll
            for (int r = 0; r < 2; ++r) {
                av[r] = __ldg(&emb4[(size_t)idxs[mmv[r]] * (DIM / 4) + kq + kqv[r]]);
                bv[r] = __ldg(&wih4[(size_t)(n0 + mmv[r]) * (DIM / 4) + kq + kqv[r]]);
            }
        }

#pragma unroll
        for (int kk = 0; kk < GBK; ++kk) {
            float4 a0 = *reinterpret_cast<const float4*>(&As[cur][kk][ty * 4]);
            float4 a1 = *reinterpret_cast<const float4*>(&As[cur][kk][64 + ty * 4]);
            float4 b0 = *reinterpret_cast<const float4*>(&Bs[cur][kk][tx * 4]);
            float4 b1 = *reinterpret_cast<const float4*>(&Bs[cur][kk][64 + tx * 4]);
            ulonglong2 bp0 = *reinterpret_cast<ulonglong2*>(&b0);
            ulonglong2 bp1 = *reinterpret_cast<ulonglong2*>(&b1);
            float avv[8] = {a0.x, a0.y, a0.z, a0.w, a1.x, a1.y, a1.z, a1.w};
#pragma unroll
            for (int i = 0; i < 8; ++i) {
                unsigned long long ap = pack2(avv[i]);
                fma2(acc[i][0], ap, bp0.x);
                fma2(acc[i][1], ap, bp0.y);
                fma2(acc[i][2], ap, bp1.x);
                fma2(acc[i][3], ap, bp1.y);
            }
        }

        if (kt < NT - 1) {
            const int nxt = 1 - cur;
#pragma unroll
            for (int r = 0; r < 2; ++r) {
                int mm = mmv[r], kc = kqv[r] * 4;
                As[nxt][kc + 0][mm] = av[r].x; As[nxt][kc + 1][mm] = av[r].y;
                As[nxt][kc + 2][mm] = av[r].z; As[nxt][kc + 3][mm] = av[r].w;
                Bs[nxt][kc + 0][mm] = bv[r].x; Bs[nxt][kc + 1][mm] = bv[r].y;
                Bs[nxt][kc + 2][mm] = bv[r].z; Bs[nxt][kc + 3][mm] = bv[r].w;
            }
            __syncthreads();
        }
    }

    float4 bs0 = *reinterpret_cast<const float4*>(&bias[tx * 4]);
    float4 bs1 = *reinterpret_cast<const float4*>(&bias[64 + tx * 4]);
#pragma unroll
    for (int i = 0; i < 8; ++i) {
        int m = m0 + ((i < 4) ? (ty * 4 + i) : (64 + ty * 4 + (i - 4)));
        float4 o0, o1;
        o0.x = lo32(acc[i][0]) + bs0.x;  o0.y = hi32(acc[i][0]) + bs0.y;
        o0.z = lo32(acc[i][1]) + bs0.z;  o0.w = hi32(acc[i][1]) + bs0.w;
        o1.x = lo32(acc[i][2]) + bs1.x;  o1.y = hi32(acc[i][2]) + bs1.y;
        o1.z = lo32(acc[i][3]) + bs1.z;  o1.w = hi32(acc[i][3]) + bs1.w;
        *reinterpret_cast<float4*>(&g_xp[(size_t)m * DIM + n0 + tx * 4])      = o0;
        *reinterpret_cast<float4*>(&g_xp[(size_t)m * DIM + n0 + 64 + tx * 4]) = o1;
    }
}

// =====================================================================
// Kernel 2: persistent RNN recurrence — merge of the two proven variants.
// Grid: (8 slices, 16 groups) = 128 co-resident CTAs, 512 threads.
// Thread (h=tid&63, js=tid>>6) owns W_hh[hs0+h][js*64..+64) in 32 f32x2
// registers; js warp-uniform -> H smem reads are broadcast LDS.128.
// Gate  (from R7, 1477us): ALL 64 threads of a js-group acquire-poll the
//   producer flag (each thread's own acquire orders its own ldcg -> no
//   propagation barrier), ldcg 1KB slice, STS, one named bar.
// Tail  (from R11): part[] parity-double-buffered -> ONE __syncthreads
//   per step; reducer warps bar9 then tid0 st.release; g_hid store after
//   release, off the critical path. WAR safety: release is ordered after
//   the join-__syncthreads; transitively all step-t gate reads of g_hbuf
//   precede any step-t+1 overwrite (unchanged from R7/R11).
// =====================================================================
#define RNN_GROUPS 16
#define RNN_SLICES 8

__device__ __forceinline__ unsigned flag_idx(int t, int s, int g) {
    return (unsigned)(((t * 8 + s) * 16 + g) * 8);
}

__global__ __launch_bounds__(512, 1) void rnn_kernel(const float* __restrict__ W_hh)
{
    __shared__ float hsm[4 * DIM];            // 8KB h state [b][col]
    __shared__ float part[2][8 * 4 * 64];     // 16KB [parity][js][b][h]

    const int tid   = threadIdx.x;
    const int slice = blockIdx.x;
    const int g     = blockIdx.y;
    const int hs0   = slice * 64;
    const int b0    = g * 4;
    const int h     = tid & 63;
    const int js    = tid >> 6;      // 0..7, warp-uniform
    const int ob    = js & 3;        // output batch for tid<256

    // --- this thread's W segment: 64 floats = 32 f32x2 regs ---
    unsigned long long w[32];
    {
        const float4* Wg4 = reinterpret_cast<const float4*>(W_hh)
                            + (size_t)(hs0 + h) * (DIM / 4) + js * 16;
#pragma unroll
        for (int k = 0; k < 16; ++k) {
            float4 v = __ldg(&Wg4[k]);
            ulonglong2 p = *reinterpret_cast<ulonglong2*>(&v);
            w[2 * k]     = p.x;
            w[2 * k + 1] = p.y;
        }
    }

    // h(0) = 0
#pragma unroll
    for (int r = 0; r < 4; ++r) hsm[r * 512 + tid] = 0.0f;

    // per-js slice-load coords: 64 threads x float4 = 1KB slice
    const int lb  = h >> 4;          // batch 0..3
    const int lc  = (h & 15) * 4;    // float offset within 64-col slice
    const int cbK = js * 16;         // ulonglong2 column base

    __syncthreads();

    for (int t = 0; t < T; ++t) {
        const int cur = t & 1;

        // ---- prefetch xp (DRAM latency hidden behind gate+matvec) ----
        float xpv = 0.0f;
        if (tid < 256)
            xpv = __ldg(&g_xp[((size_t)t * B + (b0 + ob)) * DIM + hs0 + h]);

        // ---- gate (R7 style): every thread polls, then loads its 16B ----
        if (t > 0) {
            const unsigned* fp = &g_flag[flag_idx(t, js, g)];
            unsigned v;
            do {
                asm volatile("ld.acquire.gpu.global.u32 %0, [%1];"
                             : "=r"(v) : "l"(fp) : "memory");
            } while (!v);
            const float4* src = reinterpret_cast<const float4*>(
                &g_hbuf[(size_t)cur * B * DIM
                        + (size_t)(b0 + lb) * DIM + js * 64 + lc]);
            float4 hv = __ldcg(src);
            *reinterpret_cast<float4*>(&hsm[lb * 512 + js * 64 + lc]) = hv;
            asm volatile("bar.sync %0, %1;" :: "r"(js + 1), "r"(64) : "memory");
        }

        // ---- matvec: W from registers, H via broadcast LDS ----
        const ulonglong2* H2 = reinterpret_cast<const ulonglong2*>(hsm);
        unsigned long long a0x=0,a0y=0,a1x=0,a1y=0,a2x=0,a2y=0,a3x=0,a3y=0;
#pragma unroll
        for (int k = 0; k < 16; ++k) {
            int c = cbK + k;
            ulonglong2 x0 = H2[c];
            fma2(a0x, w[2*k], x0.x); fma2(a0y, w[2*k+1], x0.y);
            ulonglong2 x1 = H2[128 + c];
            fma2(a1x, w[2*k], x1.x); fma2(a1y, w[2*k+1], x1.y);
            ulonglong2 x2 = H2[256 + c];
            fma2(a2x, w[2*k], x2.x); fma2(a2y, w[2*k+1], x2.y);
            ulonglong2 x3 = H2[384 + c];
            fma2(a3x, w[2*k], x3.x); fma2(a3y, w[2*k+1], x3.y);
        }
        float* pc = part[cur];
        pc[(js * 4 + 0) * 64 + h] = sum2(a0x) + sum2(a0y);
        pc[(js * 4 + 1) * 64 + h] = sum2(a1x) + sum2(a1y);
        pc[(js * 4 + 2) * 64 + h] = sum2(a2x) + sum2(a2y);
        pc[(js * 4 + 3) * 64 + h] = sum2(a3x) + sum2(a3y);
        __syncthreads();   // join; parity on part lets warps 8-15 run ahead

        // ---- reduce 8 partials, add xp, tanh, publish, release ----
        if (tid < 256) {
            float dot = 0.0f;
#pragma unroll
            for (int s = 0; s < 8; ++s) dot += pc[(s * 4 + ob) * 64 + h];
            float hn = tanhf(dot + xpv);
            if (t < T - 1)
                g_hbuf[(size_t)((t + 1) & 1) * B * DIM
                       + (size_t)(b0 + ob) * DIM + hs0 + h] = hn;
            asm volatile("bar.sync 9, 256;" ::: "memory");   // writer-warps join
            if (tid == 0 && t < T - 1) {
                unsigned* fp = &g_flag[flag_idx(t + 1, slice, g)];
                asm volatile("st.release.gpu.global.u32 [%0], %1;"
                             :: "l"(fp), "r"(1u) : "memory");
            }
            // lazy history store (off the critical exchange path)
            g_hid[((size_t)t * B + (b0 + ob)) * DIM + hs0 + h] = hn;
        }
        // warps 8-15 proceed straight to the next gate
    }
}

// =====================================================================
// Kernel 3: softmax over H (axis=1 of [B,H,T]) + transpose -> [b][h][t]
// =====================================================================
__global__ __launch_bounds__(256) void softmax_kernel(float* __restrict__ out)
{
    __shared__ float tile[16][513];
    __shared__ float rinv[16];

    const int tid = threadIdx.x;
    const int bb  = blockIdx.y;
    const int t0  = blockIdx.x * 16;

#pragma unroll
    for (int it = 0; it < 32; ++it) {
        int f = it * 256 + tid;
        int tt = f >> 9, hh = f & 511;
        tile[tt][hh] = __ldg(&g_hid[((size_t)(t0 + tt) * B + bb) * DIM + hh]);
    }
    __syncthreads();

    const int wid = tid >> 5, lane = tid & 31;
#pragma unroll
    for (int rr = 0; rr < 2; ++rr) {
        int tt = wid * 2 + rr;
        float m = -3.4e38f;
#pragma unroll
        for (int k = 0; k < 16; ++k) m = fmaxf(m, tile[tt][lane + 32 * k]);
#pragma unroll
        for (int off = 16; off >= 1; off >>= 1)
            m = fmaxf(m, __shfl_xor_sync(0xffffffffu, m, off));
        float s = 0.0f;
#pragma unroll
        for (int k = 0; k < 16; ++k) {
            float e = __expf(tile[tt][lane + 32 * k] - m);
            tile[tt][lane + 32 * k] = e;
            s += e;
        }
#pragma unroll
        for (int off = 16; off >= 1; off >>= 1)
            s += __shfl_xor_sync(0xffffffffu, s, off);
        if (lane == 0) rinv[tt] = 1.0f / s;
    }
    __syncthreads();

    const int hw  = tid >> 4;
    const int l16 = tid & 15;
#pragma unroll
    for (int it = 0; it < 32; ++it) {
        int hh = it * 16 + hw;
        float v = tile[l16][hh] * rinv[l16];
        out[((size_t)bb * DIM + hh) * T + t0 + l16] = v;
    }
}

// =====================================================================
extern "C" void kernel_launch(void* const* d_in, const int* in_sizes, int n_in,
                              void* d_out, int out_size)
{
    const int*   x    = (const int*)  d_in[0];
    const float* emb  = (const float*)d_in[1];
    const float* W_ih = (const float*)d_in[2];
    const float* W_hh = (const float*)d_in[3];
    const float* b_ih = (const float*)d_in[4];
    const float* b_hh = (const float*)d_in[5];
    float* out = (float*)d_out;

    void* p_flag;
    cudaGetSymbolAddress(&p_flag, g_flag);
    cudaMemsetAsync(p_flag, 0, sizeof(unsigned) * (size_t)T * 8 * 16 * 8);

    // 1) input projection GEMM -> g_xp
    gemm_xp_kernel<<<dim3(DIM / GBN, (T * B) / GBM), 256>>>(x, emb, W_ih, b_ih, b_hh);

    // 2) persistent recurrence -> g_hid
    rnn_kernel<<<dim3(RNN_SLICES, RNN_GROUPS), 512>>>(W_hh);

    // 3) softmax over H + transpose -> out
    softmax_kernel<<<dim3(T / 16, B), 256>>>(out);
}